// round 11
// baseline (speedup 1.0000x reference)
#include <cuda_runtime.h>
#include <cuda_bf16.h>
#include <cuda_fp16.h>
#include <cuda_fp8.h>
#include <cstdint>
#include <cstddef>

// Problem constants
#define BATCH   4096
#define DIM     512
#define QSIZE   32768
#define NHARD   9830
#define NRAND   22938
#define INV_T   (1.0f/0.07f)
#define KEXP    (INV_T * 1.44269504f)   // log2(e)/T
#define FP8_SCALE 16.0f
#define INV_SCALE2 (1.0f / 256.0f)

// -------- device scratch (static allocation; no cudaMalloc allowed) --------
__device__ uint8_t g_eegn8[BATCH * DIM];           // 2 MB  normalized eeg * 16, e4m3
__device__ uint8_t g_qbf8[QSIZE * DIM];            // 16 MB queue * 16, e4m3
__device__ __half  g_neg[(size_t)BATCH * QSIZE];   // 256 MB
__device__ float   g_pos[BATCH];
__device__ double  g_sums[2];

// ---------------------------------------------------------------------------
__global__ void k_zero() { g_sums[0] = 0.0; g_sums[1] = 0.0; }

__global__ __launch_bounds__(128) void k_norm(const float* __restrict__ eeg,
                                              const float* __restrict__ clip) {
    int b = blockIdx.x, t = threadIdx.x;
    float4 e = ((const float4*)(eeg  + (size_t)b * DIM))[t];
    float4 c = ((const float4*)(clip + (size_t)b * DIM))[t];
    float se = e.x*e.x + e.y*e.y + e.z*e.z + e.w*e.w;
    float sc = c.x*c.x + c.y*c.y + c.z*c.z + c.w*c.w;
    float sd = e.x*c.x + e.y*c.y + e.z*c.z + e.w*c.w;
    #pragma unroll
    for (int o = 16; o; o >>= 1) {
        se += __shfl_down_sync(0xFFFFFFFFu, se, o);
        sc += __shfl_down_sync(0xFFFFFFFFu, sc, o);
        sd += __shfl_down_sync(0xFFFFFFFFu, sd, o);
    }
    __shared__ float rs[3][4];
    __shared__ float sInvE;
    int w = t >> 5, l = t & 31;
    if (l == 0) { rs[0][w] = se; rs[1][w] = sc; rs[2][w] = sd; }
    __syncthreads();
    if (t == 0) {
        float SE = rs[0][0] + rs[0][1] + rs[0][2] + rs[0][3];
        float SC = rs[1][0] + rs[1][1] + rs[1][2] + rs[1][3];
        float SD = rs[2][0] + rs[2][1] + rs[2][2] + rs[2][3];
        float ie = 1.0f / fmaxf(sqrtf(SE), 1e-12f);
        float ic = 1.0f / fmaxf(sqrtf(SC), 1e-12f);
        sInvE = ie;
        g_pos[b] = SD * ie * ic;
    }
    __syncthreads();
    float s = sInvE * FP8_SCALE;
    float4 v = make_float4(e.x * s, e.y * s, e.z * s, e.w * s);
    __nv_fp8x4_e4m3 p(v);
    ((uint32_t*)g_eegn8)[b * (DIM / 4) + t] = *(uint32_t*)&p;
}

__global__ __launch_bounds__(256) void k_convq(const float* __restrict__ q) {
    int i = blockIdx.x * 256 + threadIdx.x;      // float4 index over QSIZE*DIM/4
    float4 v = ((const float4*)q)[i];
    v.x *= FP8_SCALE; v.y *= FP8_SCALE; v.z *= FP8_SCALE; v.w *= FP8_SCALE;
    __nv_fp8x4_e4m3 p(v);
    ((uint32_t*)g_qbf8)[i] = *(uint32_t*)&p;
}

// ---------------------------------------------------------------------------
// FP8 e4m3 mma.sync GEMM (m16n8k32), f32 accumulate.
// CTA tile 128x128, 256 threads, warp grid 4(m)x2(n), warp tile 32x64.
// 4-stage cp.async, 80KB smem -> 2 CTAs/SM.
// ---------------------------------------------------------------------------
__device__ __forceinline__ uint32_t smem_u32(const void* p) {
    return (uint32_t)__cvta_generic_to_shared(p);
}
__device__ __forceinline__ void cp16(uint32_t s, const void* g) {
    asm volatile("cp.async.cg.shared.global [%0], [%1], 16;\n" :: "r"(s), "l"(g));
}
__device__ __forceinline__ void cp_commit() { asm volatile("cp.async.commit_group;\n"); }
template <int N> __device__ __forceinline__ void cp_wait() {
    asm volatile("cp.async.wait_group %0;\n" :: "n"(N));
}

#define ROWB 80                        // 64 fp8 + 16B pad: conflict-free
#define STAGES 4
#define KTILES 8                       // DIM / 64
#define A_STAGE_B (128 * ROWB)         // 10240 B
#define B_STAGE_B (128 * ROWB)         // 10240 B
#define STAGE_B   (A_STAGE_B + B_STAGE_B)
#define GEMM_SMEM (STAGES * STAGE_B)   // 81920 B -> 2 CTAs/SM

__global__ __launch_bounds__(256, 2) void k_gemm() {
    extern __shared__ __align__(16) unsigned char smraw[];
    uint32_t sbase = smem_u32(smraw);
    int tid = threadIdx.x, warp = tid >> 5, lane = tid & 31;
    int bn = blockIdx.x, bm = blockIdx.y;
    int wm = warp & 3, wn = warp >> 2;   // 4(m) x 2(n); warp tile 32x64

    const uint8_t* Abase = g_eegn8 + (size_t)bm * 128 * DIM;
    const uint8_t* Bbase = g_qbf8  + (size_t)bn * 128 * DIM;

    auto load_stage = [&](int s, int kt) {
        uint32_t sa = sbase + s * STAGE_B;
        uint32_t sb = sa + A_STAGE_B;
        #pragma unroll
        for (int i = 0; i < 4; ++i) {               // 1024 16B chunks / 256 thr
            int c = tid + i * 256;
            uint32_t dst; const uint8_t* g; int row, col;
            if (c < 512) { row = c >> 2; col = c & 3; dst = sa;
                           g = Abase + (size_t)row * DIM + kt * 64 + col * 16; }
            else { int cb = c - 512; row = cb >> 2; col = cb & 3; dst = sb;
                   g = Bbase + (size_t)row * DIM + kt * 64 + col * 16; }
            cp16(dst + (uint32_t)(row * ROWB + col * 16), g);
        }
    };

    float acc[2][8][4];                  // f32 accumulators (64 regs)
    #pragma unroll
    for (int i = 0; i < 2; i++)
        #pragma unroll
        for (int j = 0; j < 8; j++)
            #pragma unroll
            for (int r = 0; r < 4; r++) acc[i][j][r] = 0.0f;

    // A: 2x ldmatrix.x4 per ks (32 rows x 32B k-slab). B: 4x ldmatrix.x4 (64 rows).
    int aRow = wm * 32 + (lane & 15);
    int aB0  = (lane >> 4) * 16;         // 16B half within 32B k-slab
    int bRow = wn * 64 + (lane & 7) + ((lane & 16) >> 1);
    int bB0  = ((lane >> 3) & 1) * 16;

    #pragma unroll
    for (int s = 0; s < STAGES - 1; ++s) { load_stage(s, s); cp_commit(); }

    for (int kt = 0; kt < KTILES; ++kt) {
        cp_wait<STAGES - 2>();
        __syncthreads();
        if (kt + STAGES - 1 < KTILES) load_stage((kt + STAGES - 1) % STAGES, kt + STAGES - 1);
        cp_commit();

        uint32_t sa = sbase + (kt % STAGES) * STAGE_B;
        uint32_t sb = sa + A_STAGE_B;
        #pragma unroll
        for (int ks = 0; ks < 2; ++ks) {             // k32 per step
            uint32_t fa[2][4];
            #pragma unroll
            for (int mi = 0; mi < 2; mi++) {
                uint32_t addr = sa + (uint32_t)((aRow + mi * 16) * ROWB + ks * 32 + aB0);
                asm volatile("ldmatrix.sync.aligned.m8n8.x4.shared.b16 {%0,%1,%2,%3}, [%4];\n"
                    : "=r"(fa[mi][0]), "=r"(fa[mi][1]),
                      "=r"(fa[mi][2]), "=r"(fa[mi][3]) : "r"(addr));
            }
            uint32_t fb[4][4];
            #pragma unroll
            for (int np = 0; np < 4; np++) {
                uint32_t addr = sb + (uint32_t)((bRow + np * 16) * ROWB + ks * 32 + bB0);
                asm volatile("ldmatrix.sync.aligned.m8n8.x4.shared.b16 {%0,%1,%2,%3}, [%4];\n"
                    : "=r"(fb[np][0]), "=r"(fb[np][1]),
                      "=r"(fb[np][2]), "=r"(fb[np][3]) : "r"(addr));
            }
            #pragma unroll
            for (int mi = 0; mi < 2; mi++)
                #pragma unroll
                for (int ni = 0; ni < 8; ni++) {
                    uint32_t b0 = fb[ni >> 1][(ni & 1) * 2 + 0];
                    uint32_t b1 = fb[ni >> 1][(ni & 1) * 2 + 1];
                    asm volatile(
                        "mma.sync.aligned.m16n8k32.row.col.f32.e4m3.e4m3.f32 "
                        "{%0,%1,%2,%3}, {%4,%5,%6,%7}, {%8,%9}, {%0,%1,%2,%3};\n"
                        : "+f"(acc[mi][ni][0]), "+f"(acc[mi][ni][1]),
                          "+f"(acc[mi][ni][2]), "+f"(acc[mi][ni][3])
                        : "r"(fa[mi][0]), "r"(fa[mi][1]),
                          "r"(fa[mi][2]), "r"(fa[mi][3]),
                          "r"(b0), "r"(b1));
                }
        }
    }

    // Epilogue: f32 acc * 1/256 -> fp16 store
    #pragma unroll
    for (int mi = 0; mi < 2; mi++) {
        #pragma unroll
        for (int ni = 0; ni < 8; ni++) {
            int row = bm * 128 + wm * 32 + mi * 16 + (lane >> 2);
            int col = bn * 128 + wn * 64 + ni * 8 + (lane & 3) * 2;
            *(__half2*)&g_neg[(size_t)row * QSIZE + col] =
                __floats2half2_rn(acc[mi][ni][0] * INV_SCALE2, acc[mi][ni][1] * INV_SCALE2);
            *(__half2*)&g_neg[(size_t)(row + 8) * QSIZE + col] =
                __floats2half2_rn(acc[mi][ni][2] * INV_SCALE2, acc[mi][ni][3] * INV_SCALE2);
        }
    }
}

// ---------------------------------------------------------------------------
// k_select: UNCHANGED from round 10 (1024-bin, 3 CTAs/SM).
// ---------------------------------------------------------------------------
#define SEL_T 512
#define NBIN 1024
#define CBUF_CAP 1024
#define SEL_SMEM (QSIZE*2 + NBIN*4 + CBUF_CAP*2)   // 71680 B

__device__ __forceinline__ uint32_t h2ex2(uint32_t x) {
    uint32_t r;
    asm("ex2.approx.f16x2 %0, %1;" : "=r"(r) : "r"(x));
    return r;
}

__device__ __forceinline__ void find_bin(int* hist, int target, int* scs,
                                         int* out_bin, int* out_above, int tid) {
    int base = tid * 2;
    int c = hist[base] + hist[base + 1];
    scs[tid] = c;
    __syncthreads();
    #pragma unroll
    for (int d = 1; d < SEL_T; d <<= 1) {
        int v = (tid + d < SEL_T) ? scs[tid + d] : 0;
        __syncthreads();
        scs[tid] += v;
        __syncthreads();
    }
    int Sincl = scs[tid];
    int Sexcl = (tid + 1 < SEL_T) ? scs[tid + 1] : 0;
    if (Sexcl < target && Sincl >= target) {
        int ca = Sexcl;
        #pragma unroll
        for (int j = 1; j >= 0; --j) {
            int h = hist[base + j];
            if (ca + h >= target) { *out_bin = base + j; *out_above = ca; break; }
            ca += h;
        }
    }
}

__global__ __launch_bounds__(SEL_T, 3) void k_select(const int* __restrict__ ridx) {
    extern __shared__ unsigned char dyn2[];
    __half*  srow  = (__half*)dyn2;                          // 65536 B
    __half2* srow2 = (__half2*)dyn2;
    int*     hist  = (int*)(dyn2 + QSIZE*2);                 // 4096 B
    __half*  cbuf  = (__half*)(dyn2 + QSIZE*2 + NBIN*4);     // 2048 B
    __shared__ int   scs[SEL_T];
    __shared__ float wred[SEL_T/32];
    __shared__ int   s_bin, s_above, s_nc;
    __shared__ float s_max;

    int b = blockIdx.x, tid = threadIdx.x;

    for (int i = tid; i < NBIN; i += SEL_T) hist[i] = 0;
    if (tid == 0) s_nc = 0;
    __syncthreads();

    const uint4* src = (const uint4*)(g_neg + (size_t)b * QSIZE);
    uint4* drow = (uint4*)srow;
    __half2 hm = __floats2half2_rn(-2.0f, -2.0f);
    for (int i = tid; i < QSIZE / 8; i += SEL_T) {
        uint4 v = src[i]; drow[i] = v;
        uint32_t ws[4] = {v.x, v.y, v.z, v.w};
        #pragma unroll
        for (int q = 0; q < 4; ++q) {
            __half2 h2 = *(__half2*)&ws[q];
            hm = __hmax2(hm, h2);
            float2 f = __half22float2(h2);
            int b0 = (int)((f.x + 1.0f) * 512.0f); b0 = min(max(b0, 0), NBIN - 1);
            int b1 = (int)((f.y + 1.0f) * 512.0f); b1 = min(max(b1, 0), NBIN - 1);
            atomicAdd(&hist[b0], 1);
            atomicAdd(&hist[b1], 1);
        }
    }
    float lmax = fmaxf(__low2float(hm), __high2float(hm));
    #pragma unroll
    for (int o = 16; o; o >>= 1) lmax = fmaxf(lmax, __shfl_xor_sync(0xFFFFFFFFu, lmax, o));
    if ((tid & 31) == 0) wred[tid >> 5] = lmax;
    __syncthreads();
    if (tid == 0) {
        float m = -2.0f;
        for (int w = 0; w < SEL_T/32; ++w) m = fmaxf(m, wred[w]);
        s_max = m;
    }
    __syncthreads();
    float rm = s_max;

    find_bin(hist, NHARD, scs, &s_bin, &s_above, tid);
    __syncthreads();
    int bin1 = s_bin, need = NHARD - s_above;
    float lo = (float)bin1 * (1.0f / 512.0f) - 1.0f;
    __syncthreads();

    float accx = 0.0f, accy = 0.0f;
    for (int i = tid; i < QSIZE / 2; i += SEL_T) {
        __half2 v2 = srow2[i];
        float2 f = __half22float2(v2);
        int b0 = (int)((f.x + 1.0f) * 512.0f); b0 = min(max(b0, 0), NBIN - 1);
        int b1 = (int)((f.y + 1.0f) * 512.0f); b1 = min(max(b1, 0), NBIN - 1);
        if (b0 == bin1) { int p = atomicAdd(&s_nc, 1); if (p < CBUF_CAP) cbuf[p] = __low2half(v2); }
        if (b1 == bin1) { int p = atomicAdd(&s_nc, 1); if (p < CBUF_CAP) cbuf[p] = __high2half(v2); }
        __half2 xh = __floats2half2_rn((f.x - rm) * KEXP, (f.y - rm) * KEXP);
        uint32_t eu = h2ex2(*(uint32_t*)&xh);
        __half2 e2 = *(__half2*)&eu;
        float2 ef = __half22float2(e2);
        if (b0 > bin1) accx += ef.x;
        if (b1 > bin1) accy += ef.y;
        srow2[i] = e2;
    }
    float acc = accx + accy;
    __syncthreads();

    int nc = min(s_nc, CBUF_CAP);
    for (int i = tid; i < NBIN; i += SEL_T) hist[i] = 0;
    __syncthreads();
    for (int i = tid; i < nc; i += SEL_T) {
        float s = __half2float(cbuf[i]);
        int sb = (int)((s - lo) * (512.0f * 1024.0f)); sb = min(max(sb, 0), NBIN - 1);
        atomicAdd(&hist[sb], 1);
    }
    __syncthreads();
    find_bin(hist, need, scs, &s_bin, &s_above, tid);
    __syncthreads();
    int sb1 = s_bin, above2 = s_above;
    for (int i = tid; i < nc; i += SEL_T) {
        float s = __half2float(cbuf[i]);
        int sb = (int)((s - lo) * (512.0f * 1024.0f)); sb = min(max(sb, 0), NBIN - 1);
        if (sb > sb1) acc += __expf((s - rm) * INV_T);
    }
    if (tid == 0) {
        int rem = need - above2;
        float smid = lo + ((float)sb1 + 0.5f) * (1.0f / (512.0f * 1024.0f));
        acc += (float)rem * __expf((smid - rm) * INV_T);
    }

    const int2* ri2 = (const int2*)(ridx + (size_t)b * NRAND);
    for (int i = tid; i < NRAND / 2; i += SEL_T) {
        int2 p = __ldg(ri2 + i);
        acc += __half2float(srow[p.x]) + __half2float(srow[p.y]);
    }

    #pragma unroll
    for (int o = 16; o; o >>= 1) acc += __shfl_xor_sync(0xFFFFFFFFu, acc, o);
    if ((tid & 31) == 0) wred[tid >> 5] = acc;
    __syncthreads();
    if (tid == 0) {
        float tot = 0.0f;
        for (int w = 0; w < SEL_T/32; ++w) tot += wred[w];
        float p_sh = (g_pos[b] - rm) * INV_T;
        tot += __expf(p_sh);
        atomicAdd(&g_sums[0], (double)(logf(tot) - p_sh));
        atomicAdd(&g_sums[1], (g_pos[b] >= rm) ? 1.0 : 0.0);
    }
}

__global__ void k_final(float* out, int n) {
    if (n >= 1) out[0] = (float)(g_sums[0] / (double)BATCH);
    if (n >= 2) out[1] = (float)(g_sums[1] / (double)BATCH);
}

// ---------------------------------------------------------------------------
extern "C" void kernel_launch(void* const* d_in, const int* in_sizes, int n_in,
                              void* d_out, int out_size) {
    const float* eeg   = (const float*)d_in[0];
    const float* clip  = (const float*)d_in[1];
    const float* queue = (const float*)d_in[2];
    const int*   ridx  = (const int*)d_in[3];
    float* out = (float*)d_out;

    cudaFuncSetAttribute(k_gemm,   cudaFuncAttributeMaxDynamicSharedMemorySize, GEMM_SMEM);
    cudaFuncSetAttribute(k_select, cudaFuncAttributeMaxDynamicSharedMemorySize, SEL_SMEM);

    k_zero<<<1, 1>>>();
    k_norm<<<BATCH, 128>>>(eeg, clip);
    k_convq<<<QSIZE * DIM / 4 / 256, 256>>>(queue);
    k_gemm<<<dim3(QSIZE / 128, BATCH / 128), 256, GEMM_SMEM>>>();
    k_select<<<BATCH, SEL_T, SEL_SMEM>>>(ridx);
    k_final<<<1, 1>>>(out, out_size);
}